// round 5
// baseline (speedup 1.0000x reference)
#include <cuda_runtime.h>
#include <math.h>

// ---------------------------------------------------------------------------
// Problem constants
// ---------------------------------------------------------------------------
#define TT   1024
#define BB   128
#define HH   256
#define EE   58
#define OUTD 33
#define BH   (BB*HH)                 // 32768
#define HN_OFF (TT*BB*OUTD)          // 4325376
#define CN_OFF (HN_OFF + 2*BH)       // 4390912

// Decomposition: 4 batch groups (32 rows) x 32 hidden groups (8 units) = 128 CTAs
#define GBN 4
#define MB  32
#define AS  516       // A staging stride (floats): 516%32=4 -> conflict-free rows
#define GS  36        // gates tile stride

// Shared memory layout (float offsets)
// W0: K=320 (64 x-pad + 256 h), k-pair interleaved: 160 kp x 64 = 10240
// W1: K=512 (256 y0 + 256 h1):  256 kp x 64 = 16384
// A : 32 x 516 = 16512
// G : 32 x 36  = 1152
#define OFF_W0 0
#define OFF_W1 10240
#define OFF_A  26624
#define OFF_G  43136
#define OFF_B0 44288
#define OFF_B1 44320
#define SMEM_FLOATS 44352
#define SMEM_BYTES  (SMEM_FLOATS*4)   // 177408

#define PS 260
#define PROJ_SMEM ((33*PS + 32*PS + 64)*4)

// ---------------------------------------------------------------------------
// Global scratch (static __device__ arrays: allocation-free)
// ---------------------------------------------------------------------------
__device__ __align__(16) float g_h0[2][BH];
__device__ __align__(16) float g_h1[2][BH];
__device__ __align__(16) float g_y1[(size_t)TT * BH];
__device__ unsigned g_bar[GBN];

// ---------------------------------------------------------------------------
__global__ void reset_kernel(const float* __restrict__ h0in) {
    int i = blockIdx.x * blockDim.x + threadIdx.x;
    if (i < BH) {
        g_h0[0][i] = h0in[i];
        g_h1[0][i] = h0in[BH + i];
    }
    if (i < GBN) g_bar[i] = 0u;
}

// ---------------------------------------------------------------------------
// Packed f32x2 FMA: c.lo += a.lo*b.lo ; c.hi += a.hi*b.hi
// ---------------------------------------------------------------------------
#define FFMA2(c, a, b) asm("fma.rn.f32x2 %0, %1, %2, %0;" : "+l"(c) : "l"(a), "l"(b))

__device__ __forceinline__ float pair_sum(unsigned long long p) {
    return __uint_as_float((unsigned)p) + __uint_as_float((unsigned)(p >> 32));
}

// GEMM: acc2[2][4] over K (multiple of 4). A rows at Arow0 / Arow0+AS.
// W layout: [kp][32 cols x 2] (k-pair interleaved), thread reads cols tx*4..+3.
__device__ __forceinline__ void gemm_packed(const float* __restrict__ Arow0,
                                            const float* __restrict__ Wb,
                                            int tx, int K,
                                            unsigned long long acc[2][4])
{
    const float* wp = Wb + tx*8;
#pragma unroll 4
    for (int k = 0; k < K; k += 4) {
        ulonglong2 a0 = *reinterpret_cast<const ulonglong2*>(Arow0 + k);
        ulonglong2 a1 = *reinterpret_cast<const ulonglong2*>(Arow0 + AS + k);
        const float* w = wp + (k >> 1) * 64;
        ulonglong2 w0a = *reinterpret_cast<const ulonglong2*>(w);
        ulonglong2 w0b = *reinterpret_cast<const ulonglong2*>(w + 4);
        ulonglong2 w1a = *reinterpret_cast<const ulonglong2*>(w + 64);
        ulonglong2 w1b = *reinterpret_cast<const ulonglong2*>(w + 68);

        FFMA2(acc[0][0], a0.x, w0a.x); FFMA2(acc[0][1], a0.x, w0a.y);
        FFMA2(acc[0][2], a0.x, w0b.x); FFMA2(acc[0][3], a0.x, w0b.y);
        FFMA2(acc[1][0], a1.x, w0a.x); FFMA2(acc[1][1], a1.x, w0a.y);
        FFMA2(acc[1][2], a1.x, w0b.x); FFMA2(acc[1][3], a1.x, w0b.y);

        FFMA2(acc[0][0], a0.y, w1a.x); FFMA2(acc[0][1], a0.y, w1a.y);
        FFMA2(acc[0][2], a0.y, w1b.x); FFMA2(acc[0][3], a0.y, w1b.y);
        FFMA2(acc[1][0], a1.y, w1a.x); FFMA2(acc[1][1], a1.y, w1a.y);
        FFMA2(acc[1][2], a1.y, w1b.x); FFMA2(acc[1][3], a1.y, w1b.y);
    }
}

__device__ __forceinline__ float fsigmoid(float x) {
    return __fdividef(1.0f, 1.0f + __expf(-x));
}
__device__ __forceinline__ float ftanh(float x) {
    float xc = fminf(fmaxf(x, -15.0f), 15.0f);
    float e = __expf(2.0f * xc);
    return __fdividef(e - 1.0f, e + 1.0f);
}

// Batch-group spin barrier (monotonic counter; 32 CTAs/group, all resident)
__device__ __forceinline__ void group_barrier(int gb, unsigned target) {
    __threadfence();
    __syncthreads();
    if (threadIdx.x == 0) {
        atomicAdd(&g_bar[gb], 1u);
        while (*((volatile unsigned*)&g_bar[gb]) < target) { }
        __threadfence();
    }
    __syncthreads();
}

// ---------------------------------------------------------------------------
// Persistent 2-layer LSTM: grid 128 CTAs x 128 threads
// ---------------------------------------------------------------------------
__global__ __launch_bounds__(128, 1)
void lstm_persistent(const float* __restrict__ x,
                     const float* __restrict__ c0in,
                     const float* __restrict__ Wih0, const float* __restrict__ Whh0,
                     const float* __restrict__ bih0, const float* __restrict__ bhh0,
                     const float* __restrict__ Wih1, const float* __restrict__ Whh1,
                     const float* __restrict__ bih1, const float* __restrict__ bhh1,
                     float* __restrict__ out)
{
    extern __shared__ float sm[];
    float* W0s = sm + OFF_W0;
    float* W1s = sm + OFF_W1;
    float* Asm = sm + OFF_A;
    float* Gs  = sm + OFF_G;
    float* B0s = sm + OFF_B0;
    float* B1s = sm + OFF_B1;

    const int tid = threadIdx.x;
    const int gb  = blockIdx.x >> 5;
    const int gn  = blockIdx.x & 31;
    const int b0  = gb * MB;

    // ---- stage weights (once), k-pair interleaved: [kp][j*2 + (k&1)] ----
    for (int idx = tid; idx < 32*320; idx += 128) {
        int j = idx / 320, k = idx % 320;
        int gc = ((j >> 3) << 8) + (gn << 3) + (j & 7);
        float v;
        if (k < 64) v = (k < EE) ? Wih0[gc*EE + k] : 0.0f;
        else        v = Whh0[gc*HH + (k - 64)];
        W0s[(k >> 1)*64 + j*2 + (k & 1)] = v;
    }
    for (int idx = tid; idx < 32*512; idx += 128) {
        int j = idx / 512, k = idx % 512;
        int gc = ((j >> 3) << 8) + (gn << 3) + (j & 7);
        float v = (k < 256) ? Wih1[gc*HH + k] : Whh1[gc*HH + (k - 256)];
        W1s[(k >> 1)*64 + j*2 + (k & 1)] = v;
    }
    if (tid < 32) {
        int gc = ((tid >> 3) << 8) + (gn << 3) + (tid & 7);
        B0s[tid] = bih0[gc] + bhh0[gc];
        B1s[tid] = bih1[gc] + bhh1[gc];
    }

    // elementwise mapping
    const int eb = tid & 31, q0 = tid >> 5;
    const int hg0 = (gn << 3) + q0, hg1 = hg0 + 4;
    const int bg  = b0 + eb;
    float c0r[2], c1r[2], hl0[2] = {0,0}, hl1[2] = {0,0};
    c0r[0] = c0in[bg*HH + hg0];       c0r[1] = c0in[bg*HH + hg1];
    c1r[0] = c0in[BH + bg*HH + hg0];  c1r[1] = c0in[BH + bg*HH + hg1];

    // GEMM mapping: tx = col group (4 cols), ty = row pair (rows 2ty, 2ty+1)
    const int tx = tid & 7, ty = tid >> 3;
    const float* Arow = Asm + (ty*2)*AS;

    __syncthreads();

    for (int t = 0; t < TT; ++t) {
        const int rp = t & 1, wp = rp ^ 1;

        // ---- stage 1: A = [x(64, zero-pad) | h0[t-1](256)] ----
        for (int idx = tid; idx < MB*64; idx += 128) {
            int m = idx >> 6, e = idx & 63;
            Asm[m*AS + e] = (e < EE) ? x[(size_t)t*BB*EE + (size_t)(b0+m)*EE + e] : 0.0f;
        }
        {
            const float4* src = reinterpret_cast<const float4*>(&g_h0[rp][b0*HH]);
            for (int idx = tid; idx < MB*64; idx += 128) {
                int m = idx >> 6, c = idx & 63;
                float4 v = __ldcg(src + m*64 + c);
                *reinterpret_cast<float4*>(&Asm[m*AS + 64 + c*4]) = v;
            }
        }
        __syncthreads();

        // ---- layer 0 GEMM (K=320) ----
        {
            unsigned long long acc[2][4] = {{0,0,0,0},{0,0,0,0}};
            gemm_packed(Arow, W0s, tx, 320, acc);
#pragma unroll
            for (int mi = 0; mi < 2; ++mi) {
                float4 g;
                g.x = pair_sum(acc[mi][0]) + B0s[tx*4+0];
                g.y = pair_sum(acc[mi][1]) + B0s[tx*4+1];
                g.z = pair_sum(acc[mi][2]) + B0s[tx*4+2];
                g.w = pair_sum(acc[mi][3]) + B0s[tx*4+3];
                *reinterpret_cast<float4*>(&Gs[(ty*2+mi)*GS + tx*4]) = g;
            }
        }
        __syncthreads();

        // ---- layer 0 elementwise: publish h0[t] ----
#pragma unroll
        for (int z = 0; z < 2; ++z) {
            int q = q0 + 4*z;
            float gi = Gs[eb*GS + q];
            float gf = Gs[eb*GS + 8 + q];
            float gg = Gs[eb*GS + 16 + q];
            float go = Gs[eb*GS + 24 + q];
            float iv = fsigmoid(gi), fv = fsigmoid(gf);
            float gv = ftanh(gg),    ov = fsigmoid(go);
            c0r[z] = fv * c0r[z] + iv * gv;
            float hv = ov * ftanh(c0r[z]);
            hl0[z] = hv;
            __stcg(&g_h0[wp][bg*HH + (z ? hg1 : hg0)], hv);
        }
        // single barrier per step: orders h0[t] (just written) AND h1[t-1]
        // (written before each CTA's arrival here) before stage-2 reads.
        group_barrier(gb, 32u*(t+1));

        // ---- stage 2: A = [y0 = h0[t] (256) | h1[t-1] (256)] ----
        {
            const float4* s0 = reinterpret_cast<const float4*>(&g_h0[wp][b0*HH]);
            const float4* s1 = reinterpret_cast<const float4*>(&g_h1[rp][b0*HH]);
            for (int idx = tid; idx < MB*64; idx += 128) {
                int m = idx >> 6, c = idx & 63;
                float4 v0 = __ldcg(s0 + m*64 + c);
                float4 v1 = __ldcg(s1 + m*64 + c);
                *reinterpret_cast<float4*>(&Asm[m*AS + c*4])       = v0;
                *reinterpret_cast<float4*>(&Asm[m*AS + 256 + c*4]) = v1;
            }
        }
        __syncthreads();

        // ---- layer 1 GEMM (K=512) ----
        {
            unsigned long long acc[2][4] = {{0,0,0,0},{0,0,0,0}};
            gemm_packed(Arow, W1s, tx, 512, acc);
#pragma unroll
            for (int mi = 0; mi < 2; ++mi) {
                float4 g;
                g.x = pair_sum(acc[mi][0]) + B1s[tx*4+0];
                g.y = pair_sum(acc[mi][1]) + B1s[tx*4+1];
                g.z = pair_sum(acc[mi][2]) + B1s[tx*4+2];
                g.w = pair_sum(acc[mi][3]) + B1s[tx*4+3];
                *reinterpret_cast<float4*>(&Gs[(ty*2+mi)*GS + tx*4]) = g;
            }
        }
        __syncthreads();

        // ---- layer 1 elementwise: publish h1[t] + y1 ----
#pragma unroll
        for (int z = 0; z < 2; ++z) {
            int q = q0 + 4*z;
            float gi = Gs[eb*GS + q];
            float gf = Gs[eb*GS + 8 + q];
            float gg = Gs[eb*GS + 16 + q];
            float go = Gs[eb*GS + 24 + q];
            float iv = fsigmoid(gi), fv = fsigmoid(gf);
            float gv = ftanh(gg),    ov = fsigmoid(go);
            c1r[z] = fv * c1r[z] + iv * gv;
            float hv = ov * ftanh(c1r[z]);
            hl1[z] = hv;
            int hg = z ? hg1 : hg0;
            __stcg(&g_h1[wp][bg*HH + hg], hv);
            __stcg(&g_y1[(size_t)t*BH + (size_t)bg*HH + hg], hv);
        }
        // no second barrier: next step's barrier covers h1[t] visibility.
    }

    // ---- final hn / cn ----
#pragma unroll
    for (int z = 0; z < 2; ++z) {
        int hg = z ? hg1 : hg0;
        out[HN_OFF +      bg*HH + hg] = hl0[z];
        out[HN_OFF + BH + bg*HH + hg] = hl1[z];
        out[CN_OFF +      bg*HH + hg] = c0r[z];
        out[CN_OFF + BH + bg*HH + hg] = c1r[z];
    }
}

// ---------------------------------------------------------------------------
// Output projection: out = softplus(y1 @ W_out^T + b_out)
// ---------------------------------------------------------------------------
__global__ __launch_bounds__(128)
void proj_kernel(const float* __restrict__ Wout,
                 const float* __restrict__ bout,
                 float* __restrict__ out)
{
    extern __shared__ float sm[];
    float* ws = sm;
    float* ys = sm + 33*PS;
    float* bs = sm + 33*PS + 32*PS;

    const int tid = threadIdx.x;
    const int t  = blockIdx.x >> 2;
    const int b0 = (blockIdx.x & 3) * 32;

    for (int idx = tid; idx < 33*256; idx += 128) {
        int o = idx >> 8, k = idx & 255;
        ws[o*PS + k] = Wout[idx];
    }
    if (tid < 33) bs[tid] = bout[tid];
    {
        const float* ysrc = &g_y1[(size_t)t*BH + (size_t)b0*HH];
        for (int idx = tid; idx < 32*256; idx += 128) {
            int m = idx >> 8, k = idx & 255;
            ys[m*PS + k] = ysrc[idx];
        }
    }
    __syncthreads();

    for (int oidx = tid; oidx < 33*32; oidx += 128) {
        int o = oidx >> 5, m = oidx & 31;
        const float* yp = &ys[m*PS];
        const float* wp = &ws[o*PS];
        float s = bs[o];
#pragma unroll 8
        for (int k = 0; k < 256; k += 4) {
            float4 y4 = *reinterpret_cast<const float4*>(yp + k);
            float4 w4 = *reinterpret_cast<const float4*>(wp + k);
            s += y4.x*w4.x + y4.y*w4.y + y4.z*w4.z + y4.w*w4.w;
        }
        float sp = fmaxf(s, 0.0f) + log1pf(expf(-fabsf(s)));
        out[(size_t)t*BB*OUTD + (size_t)(b0+m)*OUTD + o] = sp;
    }
}

// ---------------------------------------------------------------------------
extern "C" void kernel_launch(void* const* d_in, const int* in_sizes, int n_in,
                              void* d_out, int out_size) {
    (void)in_sizes; (void)n_in; (void)out_size;
    const float* x    = (const float*)d_in[0];
    const float* h0   = (const float*)d_in[1];
    const float* c0   = (const float*)d_in[2];
    const float* Wih0 = (const float*)d_in[3];
    const float* Whh0 = (const float*)d_in[4];
    const float* bih0 = (const float*)d_in[5];
    const float* bhh0 = (const float*)d_in[6];
    const float* Wih1 = (const float*)d_in[7];
    const float* Whh1 = (const float*)d_in[8];
    const float* bih1 = (const float*)d_in[9];
    const float* bhh1 = (const float*)d_in[10];
    const float* Wout = (const float*)d_in[11];
    const float* bout = (const float*)d_in[12];
    float* out = (float*)d_out;

    cudaFuncSetAttribute(lstm_persistent,
                         cudaFuncAttributeMaxDynamicSharedMemorySize, SMEM_BYTES);
    cudaFuncSetAttribute(proj_kernel,
                         cudaFuncAttributeMaxDynamicSharedMemorySize, PROJ_SMEM);

    reset_kernel<<<128, 256>>>(h0);
    lstm_persistent<<<128, 128, SMEM_BYTES>>>(
        x, c0, Wih0, Whh0, bih0, bhh0, Wih1, Whh1, bih1, bhh1, out);
    proj_kernel<<<4096, 128, PROJ_SMEM>>>(Wout, bout, out);
}

// round 6
// speedup vs baseline: 1.3747x; 1.3747x over previous
#include <cuda_runtime.h>
#include <math.h>

// ---------------------------------------------------------------------------
// Problem constants
// ---------------------------------------------------------------------------
#define TT   1024
#define BB   128
#define HH   256
#define EE   58
#define OUTD 33
#define BH   (BB*HH)                 // 32768
#define HN_OFF (TT*BB*OUTD)          // 4325376
#define CN_OFF (HN_OFF + 2*BH)       // 4390912

// Decomposition: 4 batch groups (32 rows) x 32 hidden groups (8 units) = 128 CTAs
#define GBN 4
#define MB  32
#define AS  516       // A staging stride (floats)
#define GS  36        // gates tile stride

// Shared memory layout (float offsets)
// W0: K=320 (64 x-pad + 256 h), k-pair interleaved [kp][col*2+(k&1)]: 160*64
// W1: K=512 (256 y0 + 256 h1): 256*64
#define OFF_W0 0
#define OFF_W1 10240
#define OFF_A  26624
#define OFF_G  43136
#define OFF_B0 44288
#define OFF_B1 44320
#define SMEM_FLOATS 44352
#define SMEM_BYTES  (SMEM_FLOATS*4)   // 177408

#define PS 260
#define PROJ_SMEM ((33*PS + 32*PS + 64)*4)

// ---------------------------------------------------------------------------
// Global scratch (static __device__ arrays: allocation-free)
// ---------------------------------------------------------------------------
__device__ __align__(16) float g_h0[2][BH];
__device__ __align__(16) float g_h1[2][BH];
__device__ __align__(16) float g_y1[(size_t)TT * BH];
__device__ unsigned g_bar[GBN];

// ---------------------------------------------------------------------------
__global__ void reset_kernel(const float* __restrict__ h0in) {
    int i = blockIdx.x * blockDim.x + threadIdx.x;
    if (i < BH) {
        g_h0[0][i] = h0in[i];
        g_h1[0][i] = h0in[BH + i];
    }
    if (i < GBN) g_bar[i] = 0u;
}

// ---------------------------------------------------------------------------
// Packed f32x2 FMA: c.lo += a.lo*b.lo ; c.hi += a.hi*b.hi
// ---------------------------------------------------------------------------
#define FFMA2(c, a, b) asm("fma.rn.f32x2 %0, %1, %2, %0;" : "+l"(c) : "l"(a), "l"(b))

__device__ __forceinline__ float pair_sum(unsigned long long p) {
    return __uint_as_float((unsigned)p) + __uint_as_float((unsigned)(p >> 32));
}

// GEMM: acc2[2][4] over K (multiple of 4). A rows at Arow0 / Arow0+AS.
// W layout: [kp][32 cols x 2] (k-pair interleaved); thread covers cols tx*4..+3.
// Lane remap (done by caller) guarantees every quarter-warp reads a contiguous
// 128B W chunk (4 tx x 16B, broadcast over 2 ty) -> conflict-free.
__device__ __forceinline__ void gemm_packed(const float* __restrict__ Arow0,
                                            const float* __restrict__ Wb,
                                            int tx, int K,
                                            unsigned long long acc[2][4])
{
    const float* wp = Wb + tx*8;
#pragma unroll 4
    for (int k = 0; k < K; k += 4) {
        ulonglong2 a0 = *reinterpret_cast<const ulonglong2*>(Arow0 + k);
        ulonglong2 a1 = *reinterpret_cast<const ulonglong2*>(Arow0 + AS + k);
        const float* w = wp + (k >> 1) * 64;
        ulonglong2 w0a = *reinterpret_cast<const ulonglong2*>(w);
        ulonglong2 w0b = *reinterpret_cast<const ulonglong2*>(w + 4);
        ulonglong2 w1a = *reinterpret_cast<const ulonglong2*>(w + 64);
        ulonglong2 w1b = *reinterpret_cast<const ulonglong2*>(w + 68);

        FFMA2(acc[0][0], a0.x, w0a.x); FFMA2(acc[0][1], a0.x, w0a.y);
        FFMA2(acc[0][2], a0.x, w0b.x); FFMA2(acc[0][3], a0.x, w0b.y);
        FFMA2(acc[1][0], a1.x, w0a.x); FFMA2(acc[1][1], a1.x, w0a.y);
        FFMA2(acc[1][2], a1.x, w0b.x); FFMA2(acc[1][3], a1.x, w0b.y);

        FFMA2(acc[0][0], a0.y, w1a.x); FFMA2(acc[0][1], a0.y, w1a.y);
        FFMA2(acc[0][2], a0.y, w1b.x); FFMA2(acc[0][3], a0.y, w1b.y);
        FFMA2(acc[1][0], a1.y, w1a.x); FFMA2(acc[1][1], a1.y, w1a.y);
        FFMA2(acc[1][2], a1.y, w1b.x); FFMA2(acc[1][3], a1.y, w1b.y);
    }
}

__device__ __forceinline__ float fsigmoid(float x) {
    return __fdividef(1.0f, 1.0f + __expf(-x));
}
__device__ __forceinline__ float ftanh(float x) {
    float xc = fminf(fmaxf(x, -15.0f), 15.0f);
    float e = __expf(2.0f * xc);
    return __fdividef(e - 1.0f, e + 1.0f);
}

// Batch-group spin barrier (monotonic counter; 32 CTAs/group, all resident)
__device__ __forceinline__ void group_barrier(int gb, unsigned target) {
    __threadfence();
    __syncthreads();
    if (threadIdx.x == 0) {
        atomicAdd(&g_bar[gb], 1u);
        while (*((volatile unsigned*)&g_bar[gb]) < target) { }
        __threadfence();
    }
    __syncthreads();
}

// ---------------------------------------------------------------------------
// Persistent 2-layer LSTM: grid 128 CTAs x 128 threads
// ---------------------------------------------------------------------------
__global__ __launch_bounds__(128, 1)
void lstm_persistent(const float* __restrict__ x,
                     const float* __restrict__ c0in,
                     const float* __restrict__ Wih0, const float* __restrict__ Whh0,
                     const float* __restrict__ bih0, const float* __restrict__ bhh0,
                     const float* __restrict__ Wih1, const float* __restrict__ Whh1,
                     const float* __restrict__ bih1, const float* __restrict__ bhh1,
                     float* __restrict__ out)
{
    extern __shared__ float sm[];
    float* W0s = sm + OFF_W0;
    float* W1s = sm + OFF_W1;
    float* Asm = sm + OFF_A;
    float* Gs  = sm + OFF_G;
    float* B0s = sm + OFF_B0;
    float* B1s = sm + OFF_B1;

    const int tid = threadIdx.x;
    const int gb  = blockIdx.x >> 5;
    const int gn  = blockIdx.x & 31;
    const int b0  = gb * MB;

    // ---- stage weights (once), k-pair interleaved: [kp][j*2 + (k&1)] ----
    for (int idx = tid; idx < 32*320; idx += 128) {
        int j = idx / 320, k = idx % 320;
        int gc = ((j >> 3) << 8) + (gn << 3) + (j & 7);
        float v;
        if (k < 64) v = (k < EE) ? Wih0[gc*EE + k] : 0.0f;
        else        v = Whh0[gc*HH + (k - 64)];
        W0s[(k >> 1)*64 + j*2 + (k & 1)] = v;
    }
    for (int idx = tid; idx < 32*512; idx += 128) {
        int j = idx / 512, k = idx % 512;
        int gc = ((j >> 3) << 8) + (gn << 3) + (j & 7);
        float v = (k < 256) ? Wih1[gc*HH + k] : Whh1[gc*HH + (k - 256)];
        W1s[(k >> 1)*64 + j*2 + (k & 1)] = v;
    }
    if (tid < 32) {
        int gc = ((tid >> 3) << 8) + (gn << 3) + (tid & 7);
        B0s[tid] = bih0[gc] + bhh0[gc];
        B1s[tid] = bih1[gc] + bhh1[gc];
    }

    // elementwise mapping (independent of GEMM mapping)
    const int eb = tid & 31, q0 = tid >> 5;
    const int hg0 = (gn << 3) + q0, hg1 = hg0 + 4;
    const int bg  = b0 + eb;
    float c0r[2], c1r[2], hl0[2] = {0,0}, hl1[2] = {0,0};
    c0r[0] = c0in[bg*HH + hg0];       c0r[1] = c0in[bg*HH + hg1];
    c1r[0] = c0in[BH + bg*HH + hg0];  c1r[1] = c0in[BH + bg*HH + hg1];

    // GEMM mapping: conflict-free lane remap.
    // lane bits: [1:0]->tx low, [2]->ty low, [3]->ty mid, [4]->tx high
    const int lane = tid & 31, warp = tid >> 5;
    const int tx = (lane & 3) + ((lane & 16) >> 2);          // 0..7 col group
    const int ty = warp*4 + ((lane >> 3) & 1)*2 + ((lane >> 2) & 1); // 0..15 row pair
    const float* Arow = Asm + (ty*2)*AS;

    __syncthreads();

    for (int t = 0; t < TT; ++t) {
        const int rp = t & 1, wp = rp ^ 1;

        // ---- stage 1: A = [x(64, zero-pad) | h0[t-1](256)] ----
        for (int idx = tid; idx < MB*64; idx += 128) {
            int m = idx >> 6, e = idx & 63;
            Asm[m*AS + e] = (e < EE) ? x[(size_t)t*BB*EE + (size_t)(b0+m)*EE + e] : 0.0f;
        }
        {
            const float4* src = reinterpret_cast<const float4*>(&g_h0[rp][b0*HH]);
            for (int idx = tid; idx < MB*64; idx += 128) {
                int m = idx >> 6, c = idx & 63;
                float4 v = __ldcg(src + m*64 + c);
                *reinterpret_cast<float4*>(&Asm[m*AS + 64 + c*4]) = v;
            }
        }
        __syncthreads();

        // ---- layer 0 GEMM (K=320) ----
        {
            unsigned long long acc[2][4] = {{0,0,0,0},{0,0,0,0}};
            gemm_packed(Arow, W0s, tx, 320, acc);
#pragma unroll
            for (int mi = 0; mi < 2; ++mi) {
                float4 g;
                g.x = pair_sum(acc[mi][0]) + B0s[tx*4+0];
                g.y = pair_sum(acc[mi][1]) + B0s[tx*4+1];
                g.z = pair_sum(acc[mi][2]) + B0s[tx*4+2];
                g.w = pair_sum(acc[mi][3]) + B0s[tx*4+3];
                *reinterpret_cast<float4*>(&Gs[(ty*2+mi)*GS + tx*4]) = g;
            }
        }
        __syncthreads();

        // ---- layer 0 elementwise: publish h0[t] ----
#pragma unroll
        for (int z = 0; z < 2; ++z) {
            int q = q0 + 4*z;
            float gi = Gs[eb*GS + q];
            float gf = Gs[eb*GS + 8 + q];
            float gg = Gs[eb*GS + 16 + q];
            float go = Gs[eb*GS + 24 + q];
            float iv = fsigmoid(gi), fv = fsigmoid(gf);
            float gv = ftanh(gg),    ov = fsigmoid(go);
            c0r[z] = fv * c0r[z] + iv * gv;
            float hv = ov * ftanh(c0r[z]);
            hl0[z] = hv;
            __stcg(&g_h0[wp][bg*HH + (z ? hg1 : hg0)], hv);
        }
        // single barrier per step: orders h0[t] (just written) AND h1[t-1]
        // (written before each CTA's arrival here) before stage-2 reads.
        group_barrier(gb, 32u*(t+1));

        // ---- stage 2: A = [y0 = h0[t] (256) | h1[t-1] (256)] ----
        {
            const float4* s0 = reinterpret_cast<const float4*>(&g_h0[wp][b0*HH]);
            const float4* s1 = reinterpret_cast<const float4*>(&g_h1[rp][b0*HH]);
            for (int idx = tid; idx < MB*64; idx += 128) {
                int m = idx >> 6, c = idx & 63;
                float4 v0 = __ldcg(s0 + m*64 + c);
                float4 v1 = __ldcg(s1 + m*64 + c);
                *reinterpret_cast<float4*>(&Asm[m*AS + c*4])       = v0;
                *reinterpret_cast<float4*>(&Asm[m*AS + 256 + c*4]) = v1;
            }
        }
        __syncthreads();

        // ---- layer 1 GEMM (K=512) ----
        {
            unsigned long long acc[2][4] = {{0,0,0,0},{0,0,0,0}};
            gemm_packed(Arow, W1s, tx, 512, acc);
#pragma unroll
            for (int mi = 0; mi < 2; ++mi) {
                float4 g;
                g.x = pair_sum(acc[mi][0]) + B1s[tx*4+0];
                g.y = pair_sum(acc[mi][1]) + B1s[tx*4+1];
                g.z = pair_sum(acc[mi][2]) + B1s[tx*4+2];
                g.w = pair_sum(acc[mi][3]) + B1s[tx*4+3];
                *reinterpret_cast<float4*>(&Gs[(ty*2+mi)*GS + tx*4]) = g;
            }
        }
        __syncthreads();

        // ---- layer 1 elementwise: publish h1[t] + y1 ----
#pragma unroll
        for (int z = 0; z < 2; ++z) {
            int q = q0 + 4*z;
            float gi = Gs[eb*GS + q];
            float gf = Gs[eb*GS + 8 + q];
            float gg = Gs[eb*GS + 16 + q];
            float go = Gs[eb*GS + 24 + q];
            float iv = fsigmoid(gi), fv = fsigmoid(gf);
            float gv = ftanh(gg),    ov = fsigmoid(go);
            c1r[z] = fv * c1r[z] + iv * gv;
            float hv = ov * ftanh(c1r[z]);
            hl1[z] = hv;
            int hg = z ? hg1 : hg0;
            __stcg(&g_h1[wp][bg*HH + hg], hv);
            __stcg(&g_y1[(size_t)t*BH + (size_t)bg*HH + hg], hv);
        }
        // no second barrier: next step's barrier covers h1[t] visibility.
    }

    // ---- final hn / cn ----
#pragma unroll
    for (int z = 0; z < 2; ++z) {
        int hg = z ? hg1 : hg0;
        out[HN_OFF +      bg*HH + hg] = hl0[z];
        out[HN_OFF + BH + bg*HH + hg] = hl1[z];
        out[CN_OFF +      bg*HH + hg] = c0r[z];
        out[CN_OFF + BH + bg*HH + hg] = c1r[z];
    }
}

// ---------------------------------------------------------------------------
// Output projection: out = softplus(y1 @ W_out^T + b_out)
// ---------------------------------------------------------------------------
__global__ __launch_bounds__(128)
void proj_kernel(const float* __restrict__ Wout,
                 const float* __restrict__ bout,
                 float* __restrict__ out)
{
    extern __shared__ float sm[];
    float* ws = sm;
    float* ys = sm + 33*PS;
    float* bs = sm + 33*PS + 32*PS;

    const int tid = threadIdx.x;
    const int t  = blockIdx.x >> 2;
    const int b0 = (blockIdx.x & 3) * 32;

    for (int idx = tid; idx < 33*256; idx += 128) {
        int o = idx >> 8, k = idx & 255;
        ws[o*PS + k] = Wout[idx];
    }
    if (tid < 33) bs[tid] = bout[tid];
    {
        const float* ysrc = &g_y1[(size_t)t*BH + (size_t)b0*HH];
        for (int idx = tid; idx < 32*256; idx += 128) {
            int m = idx >> 8, k = idx & 255;
            ys[m*PS + k] = ysrc[idx];
        }
    }
    __syncthreads();

    for (int oidx = tid; oidx < 33*32; oidx += 128) {
        int o = oidx >> 5, m = oidx & 31;
        const float* yp = &ys[m*PS];
        const float* wpp = &ws[o*PS];
        float s = bs[o];
#pragma unroll 8
        for (int k = 0; k < 256; k += 4) {
            float4 y4 = *reinterpret_cast<const float4*>(yp + k);
            float4 w4 = *reinterpret_cast<const float4*>(wpp + k);
            s += y4.x*w4.x + y4.y*w4.y + y4.z*w4.z + y4.w*w4.w;
        }
        float sp = fmaxf(s, 0.0f) + log1pf(expf(-fabsf(s)));
        out[(size_t)t*BB*OUTD + (size_t)(b0+m)*OUTD + o] = sp;
    }
}

// ---------------------------------------------------------------------------
extern "C" void kernel_launch(void* const* d_in, const int* in_sizes, int n_in,
                              void* d_out, int out_size) {
    (void)in_sizes; (void)n_in; (void)out_size;
    const float* x    = (const float*)d_in[0];
    const float* h0   = (const float*)d_in[1];
    const float* c0   = (const float*)d_in[2];
    const float* Wih0 = (const float*)d_in[3];
    const float* Whh0 = (const float*)d_in[4];
    const float* bih0 = (const float*)d_in[5];
    const float* bhh0 = (const float*)d_in[6];
    const float* Wih1 = (const float*)d_in[7];
    const float* Whh1 = (const float*)d_in[8];
    const float* bih1 = (const float*)d_in[9];
    const float* bhh1 = (const float*)d_in[10];
    const float* Wout = (const float*)d_in[11];
    const float* bout = (const float*)d_in[12];
    float* out = (float*)d_out;

    cudaFuncSetAttribute(lstm_persistent,
                         cudaFuncAttributeMaxDynamicSharedMemorySize, SMEM_BYTES);
    cudaFuncSetAttribute(proj_kernel,
                         cudaFuncAttributeMaxDynamicSharedMemorySize, PROJ_SMEM);

    reset_kernel<<<128, 256>>>(h0);
    lstm_persistent<<<128, 128, SMEM_BYTES>>>(
        x, c0, Wih0, Whh0, bih0, bhh0, Wih1, Whh1, bih1, bhh1, out);
    proj_kernel<<<4096, 128, PROJ_SMEM>>>(Wout, bout, out);
}